// round 15
// baseline (speedup 1.0000x reference)
#include <cuda_runtime.h>
#include <cuda_fp16.h>

#define TD    512   // timesteps
#define BD    512   // batch
#define HID   32    // hidden
#define G4    128   // 4*HID gate rows
#define EMBD  32
#define VOCAB 1000
#define FF    16
#define NCLS  7

// ---------------- scratch (static device globals; no runtime allocation) ----
// table layout: [v][unit][gate i,f,g,o]  (float4 per unit)
__device__ float g_table[VOCAB * G4];                       // 512 KB
__device__ float g_hs[(size_t)BD * TD * HID];               // 33.5 MB, (B,T,H)

// ---------------- helpers ---------------------------------------------------
__device__ __forceinline__ unsigned long long pk(float lo, float hi) {
    unsigned long long r;
    asm("mov.b64 %0, {%1,%2};" : "=l"(r) : "f"(lo), "f"(hi));
    return r;
}
__device__ __forceinline__ void upk(unsigned long long p, float& lo, float& hi) {
    asm("mov.b64 {%0,%1}, %2;" : "=f"(lo), "=f"(hi) : "l"(p));
}
__device__ __forceinline__ unsigned long long fma2(unsigned long long a,
                                                   unsigned long long b,
                                                   unsigned long long c) {
    unsigned long long d;
    asm("fma.rn.f32x2 %0, %1, %2, %3;" : "=l"(d) : "l"(a), "l"(b), "l"(c));
    return d;
}
__device__ __forceinline__ float tanh_ap(float x) {
    float y;
    asm("tanh.approx.f32 %0, %1;" : "=f"(y) : "f"(x));
    return y;
}
__device__ __forceinline__ float sigmoid_ap(float x) {
    return fmaf(tanh_ap(0.5f * x), 0.5f, 0.5f);
}
__device__ __forceinline__ __half2 u2h2(unsigned int u) {
    return *reinterpret_cast<__half2*>(&u);
}

// ---------------- K0: gate table  table[v][unit][gate] ----------------------
__global__ __launch_bounds__(256, 1)
void table_kernel(const float* __restrict__ emb,
                  const float* __restrict__ W_ih,
                  const float* __restrict__ b_ih,
                  const float* __restrict__ b_hh) {
    int tid  = threadIdx.x;
    int r    = tid & 127;        // gate-major row: gate = r>>5, unit = r&31
    int slot = tid >> 7;
    int v0   = blockIdx.x * 8;
    int gate = r >> 5, unit = r & 31;

    float4 w[8];
    const float4* wr = (const float4*)(W_ih + r * EMBD);
#pragma unroll
    for (int i = 0; i < 8; i++) w[i] = __ldg(wr + i);
    float bias = __ldg(b_ih + r) + __ldg(b_hh + r);

#pragma unroll
    for (int vo = 0; vo < 4; vo++) {
        int v = v0 + vo * 2 + slot;
        const float4* er = (const float4*)(emb + v * EMBD);
        float a0 = bias, a1 = 0.f, a2 = 0.f, a3 = 0.f;
#pragma unroll
        for (int i = 0; i < 8; i += 4) {
            float4 e0 = __ldg(er + i + 0);
            float4 e1 = __ldg(er + i + 1);
            float4 e2 = __ldg(er + i + 2);
            float4 e3 = __ldg(er + i + 3);
            a0 += w[i + 0].x * e0.x + w[i + 0].y * e0.y + w[i + 0].z * e0.z + w[i + 0].w * e0.w;
            a1 += w[i + 1].x * e1.x + w[i + 1].y * e1.y + w[i + 1].z * e1.z + w[i + 1].w * e1.w;
            a2 += w[i + 2].x * e2.x + w[i + 2].y * e2.y + w[i + 2].z * e2.z + w[i + 2].w * e2.w;
            a3 += w[i + 3].x * e3.x + w[i + 3].y * e3.y + w[i + 3].z * e3.z + w[i + 3].w * e3.w;
        }
        g_table[v * G4 + unit * 4 + gate] = (a0 + a1) + (a2 + a3);
    }
}

// ---------------- K1: LSTM — TWO batch elements per warp, fp16 dot ----------
// lane = hidden unit. Two independent recurrence chains share W2 (64 regs);
// xg pipeline stored as packed fp16 (8 regs, not 48) so ptxas doesn't spill.
// Grid: 128 CTAs x 64 threads (2 warps/CTA) = 256 warps, each owning 2 elems.
__global__ __launch_bounds__(64, 1)
void lstm_kernel(const int* __restrict__ x, const float* __restrict__ W_hh) {
    __shared__ __align__(16) __half2 hbuf[2][2][2][HID / 2]; // [warp][elem][parity][pair]
    int warp = threadIdx.x >> 5;
    int lane = threadIdx.x & 31;
    int b0   = blockIdx.x * 4 + warp * 2;
    int b1   = b0 + 1;

    // ---- weights: rows i,f,g,o for this unit as half2 pairs over h (shared) --
    __half2 W2[4][HID / 2];                                  // 64 regs
#pragma unroll
    for (int g = 0; g < 4; g++) {
        const float4* p = (const float4*)(W_hh + (g * HID + lane) * HID);
#pragma unroll
        for (int i = 0; i < 8; i++) {
            float4 rv = __ldg(p + i);
            W2[g][2 * i + 0] = __floats2half2_rn(rv.x, rv.y);
            W2[g][2 * i + 1] = __floats2half2_rn(rv.z, rv.w);
        }
    }

    if (lane < HID / 2) {
        hbuf[warp][0][0][lane] = __float2half2_rn(0.f);
        hbuf[warp][0][1][lane] = __float2half2_rn(0.f);
        hbuf[warp][1][0][lane] = __float2half2_rn(0.f);
        hbuf[warp][1][1][lane] = __float2half2_rn(0.f);
    }
    __syncwarp();

    const float4* tab4 = (const float4*)g_table;   // 32 float4 per vocab row

    // index pipeline depth 6; xg pipeline depth 3, stages packed fp16
    int A3 = x[0 * BD + b0], B3 = x[0 * BD + b1];
    int A4 = x[1 * BD + b0], B4 = x[1 * BD + b1];
    int A5 = x[2 * BD + b0], B5 = x[2 * BD + b1];
    __half2 XifA0, XgoA0, XifB0, XgoB0;
    __half2 XifA1, XgoA1, XifB1, XgoB1;
    __half2 XifA2, XgoA2, XifB2, XgoB2;
    {
        float4 xa = __ldg(tab4 + A3 * 32 + lane), xb = __ldg(tab4 + B3 * 32 + lane);
        XifA0 = __floats2half2_rn(xa.x, xa.y); XgoA0 = __floats2half2_rn(xa.z, xa.w);
        XifB0 = __floats2half2_rn(xb.x, xb.y); XgoB0 = __floats2half2_rn(xb.z, xb.w);
        xa = __ldg(tab4 + A4 * 32 + lane); xb = __ldg(tab4 + B4 * 32 + lane);
        XifA1 = __floats2half2_rn(xa.x, xa.y); XgoA1 = __floats2half2_rn(xa.z, xa.w);
        XifB1 = __floats2half2_rn(xb.x, xb.y); XgoB1 = __floats2half2_rn(xb.z, xb.w);
        xa = __ldg(tab4 + A5 * 32 + lane); xb = __ldg(tab4 + B5 * 32 + lane);
        XifA2 = __floats2half2_rn(xa.x, xa.y); XgoA2 = __floats2half2_rn(xa.z, xa.w);
        XifB2 = __floats2half2_rn(xb.x, xb.y); XgoB2 = __floats2half2_rn(xb.z, xb.w);
    }
    A3 = x[3 * BD + b0]; B3 = x[3 * BD + b1];
    A4 = x[4 * BD + b0]; B4 = x[4 * BD + b1];
    A5 = x[5 * BD + b0]; B5 = x[5 * BD + b1];

    float cA = 0.f, cB = 0.f;
    float* hsA = g_hs + (size_t)b0 * TD * HID;
    float* hsB = g_hs + (size_t)b1 * TD * HID;

    for (int t = 0; t < TD; t++) {
        // prefetch xg for t+3 (convert to fp16 immediately), index for t+6
        float4 xa = __ldg(tab4 + A3 * 32 + lane);
        float4 xb = __ldg(tab4 + B3 * 32 + lane);
        __half2 nifA = __floats2half2_rn(xa.x, xa.y), ngoA = __floats2half2_rn(xa.z, xa.w);
        __half2 nifB = __floats2half2_rn(xb.x, xb.y), ngoB = __floats2half2_rn(xb.z, xb.w);
        int nA = 0, nB = 0;
        if (t + 6 < TD) { nA = x[(t + 6) * BD + b0]; nB = x[(t + 6) * BD + b1]; }

        // unpack current xg stage to fp32
        float2 xifA = __half22float2(XifA0), xgoA = __half22float2(XgoA0);
        float2 xifB = __half22float2(XifB0), xgoB = __half22float2(XgoB0);

        // load h tiles for both elements (4+4 LDS.128, broadcast)
        const uint4* hqA = (const uint4*)hbuf[warp][0][t & 1];
        const uint4* hqB = (const uint4*)hbuf[warp][1][t & 1];
        uint4 qa0 = hqA[0], qa1 = hqA[1], qa2 = hqA[2], qa3 = hqA[3];
        uint4 qb0 = hqB[0], qb1 = hqB[1], qb2 = hqB[2], qb3 = hqB[3];
        __half2 hA[HID / 2], hB[HID / 2];
        hA[0]  = u2h2(qa0.x); hA[1]  = u2h2(qa0.y); hA[2]  = u2h2(qa0.z); hA[3]  = u2h2(qa0.w);
        hA[4]  = u2h2(qa1.x); hA[5]  = u2h2(qa1.y); hA[6]  = u2h2(qa1.z); hA[7]  = u2h2(qa1.w);
        hA[8]  = u2h2(qa2.x); hA[9]  = u2h2(qa2.y); hA[10] = u2h2(qa2.z); hA[11] = u2h2(qa2.w);
        hA[12] = u2h2(qa3.x); hA[13] = u2h2(qa3.y); hA[14] = u2h2(qa3.z); hA[15] = u2h2(qa3.w);
        hB[0]  = u2h2(qb0.x); hB[1]  = u2h2(qb0.y); hB[2]  = u2h2(qb0.z); hB[3]  = u2h2(qb0.w);
        hB[4]  = u2h2(qb1.x); hB[5]  = u2h2(qb1.y); hB[6]  = u2h2(qb1.z); hB[7]  = u2h2(qb1.w);
        hB[8]  = u2h2(qb2.x); hB[9]  = u2h2(qb2.y); hB[10] = u2h2(qb2.z); hB[11] = u2h2(qb2.w);
        hB[12] = u2h2(qb3.x); hB[13] = u2h2(qb3.y); hB[14] = u2h2(qb3.z); hB[15] = u2h2(qb3.w);

        // dot: 4 chains per element (1 per gate), depth 16 — 128 HFMA2 total
        __half2 z = __float2half2_rn(0.f);
        __half2 aA[4] = {z, z, z, z};
        __half2 aB[4] = {z, z, z, z};
#pragma unroll
        for (int k = 0; k < HID / 2; k++) {
#pragma unroll
            for (int g = 0; g < 4; g++) {
                aA[g] = __hfma2(W2[g][k], hA[k], aA[g]);
                aB[g] = __hfma2(W2[g][k], hB[k], aB[g]);
            }
        }
        // fold (cross-half) + fp32 combine with xg
        float2 vAi = __half22float2(aA[0]), vAf = __half22float2(aA[1]);
        float2 vAg = __half22float2(aA[2]), vAo = __half22float2(aA[3]);
        float2 vBi = __half22float2(aB[0]), vBf = __half22float2(aB[1]);
        float2 vBg = __half22float2(aB[2]), vBo = __half22float2(aB[3]);
        float aiA = xifA.x + (vAi.x + vAi.y);
        float afA = xifA.y + (vAf.x + vAf.y);
        float agA = xgoA.x + (vAg.x + vAg.y);
        float aoA = xgoA.y + (vAo.x + vAo.y);
        float aiB = xifB.x + (vBi.x + vBi.y);
        float afB = xifB.y + (vBf.x + vBf.y);
        float agB = xgoB.x + (vBg.x + vBg.y);
        float aoB = xgoB.y + (vBo.x + vBo.y);

        // fp32 scalar activations — two independent latency chains
        float ivA = sigmoid_ap(aiA), fvA = sigmoid_ap(afA);
        float gvA = tanh_ap(agA),    ovA = sigmoid_ap(aoA);
        float ivB = sigmoid_ap(aiB), fvB = sigmoid_ap(afB);
        float gvB = tanh_ap(agB),    ovB = sigmoid_ap(aoB);

        cA = fmaf(fvA, cA, ivA * gvA);
        cB = fmaf(fvB, cB, ivB * gvB);
        float hAn = ovA * tanh_ap(cA);
        float hBn = ovB * tanh_ap(cB);

        ((__half*)hbuf[warp][0][(t + 1) & 1])[lane] = __float2half_rn(hAn);
        ((__half*)hbuf[warp][1][(t + 1) & 1])[lane] = __float2half_rn(hBn);
        hsA[t * HID + lane] = hAn;
        hsB[t * HID + lane] = hBn;
        __syncwarp();

        XifA0 = XifA1; XgoA0 = XgoA1; XifA1 = XifA2; XgoA1 = XgoA2;
        XifA2 = nifA;  XgoA2 = ngoA;
        XifB0 = XifB1; XgoB0 = XgoB1; XifB1 = XifB2; XgoB1 = XgoB2;
        XifB2 = nifB;  XgoB2 = ngoB;
        A3 = A4; A4 = A5; A5 = nA;
        B3 = B4; B4 = B5; B5 = nB;
    }
}

// ---------------- K2: fused FF head + softmax over T ------------------------
__global__ __launch_bounds__(256, 1)
void head_softmax_kernel(const float* __restrict__ W1, const float* __restrict__ b1,
                         const float* __restrict__ W2, const float* __restrict__ b2,
                         float* __restrict__ out) {
    __shared__ unsigned long long W1p[FF * HID];
    __shared__ unsigned long long W2p[NCLS * FF];
    __shared__ float b1s[FF], b2s[NCLS];
    __shared__ float wredm[8][NCLS], wreds[8][NCLS];

    int tid = threadIdx.x;
    for (int i = tid; i < FF * HID; i += 256) { float w = W1[i]; W1p[i] = pk(w, w); }
    if (tid < NCLS * FF) { float w = W2[tid]; W2p[tid] = pk(w, w); }
    if (tid < FF)   b1s[tid] = b1[tid];
    if (tid < NCLS) b2s[tid] = b2[tid];
    __syncthreads();

    int b  = blockIdx.x;
    int t0 = tid * 2;
    const float* hr = g_hs + ((size_t)b * TD + t0) * HID;

    unsigned long long h2[HID];
#pragma unroll
    for (int k4 = 0; k4 < HID / 4; k4++) {
        float4 u = ((const float4*)hr)[k4];
        float4 v = ((const float4*)(hr + HID))[k4];
        h2[k4 * 4 + 0] = pk(u.x, v.x);
        h2[k4 * 4 + 1] = pk(u.y, v.y);
        h2[k4 * 4 + 2] = pk(u.z, v.z);
        h2[k4 * 4 + 3] = pk(u.w, v.w);
    }

    unsigned long long z2[FF];
#pragma unroll
    for (int f = 0; f < FF; f++) {
        unsigned long long acc = pk(b1s[f], b1s[f]);
#pragma unroll
        for (int k = 0; k < HID; k++) acc = fma2(W1p[f * HID + k], h2[k], acc);
        float lo, hi; upk(acc, lo, hi);
        z2[f] = pk(fmaxf(lo, 0.f), fmaxf(hi, 0.f));
    }

    float va[NCLS], vb[NCLS];
#pragma unroll
    for (int c = 0; c < NCLS; c++) {
        unsigned long long acc = pk(b2s[c], b2s[c]);
#pragma unroll
        for (int k = 0; k < FF; k++) acc = fma2(W2p[c * FF + k], z2[k], acc);
        upk(acc, va[c], vb[c]);
    }

    // --- softmax over T (across the whole CTA) ---
    int wid = tid >> 5, lid = tid & 31;
    float vm[NCLS];
#pragma unroll
    for (int c = 0; c < NCLS; c++) vm[c] = fmaxf(va[c], vb[c]);
#pragma unroll
    for (int off = 16; off; off >>= 1)
#pragma unroll
        for (int c = 0; c < NCLS; c++)
            vm[c] = fmaxf(vm[c], __shfl_xor_sync(0xffffffffu, vm[c], off));
    if (lid == 0)
#pragma unroll
        for (int c = 0; c < NCLS; c++) wredm[wid][c] = vm[c];
    __syncthreads();
    float gmax[NCLS];
#pragma unroll
    for (int c = 0; c < NCLS; c++) {
        float m = wredm[0][c];
#pragma unroll
        for (int w = 1; w < 8; w++) m = fmaxf(m, wredm[w][c]);
        gmax[c] = m;
    }
    float sm[NCLS];
#pragma unroll
    for (int c = 0; c < NCLS; c++) {
        va[c] = __expf(va[c] - gmax[c]);
        vb[c] = __expf(vb[c] - gmax[c]);
        sm[c] = va[c] + vb[c];
    }
#pragma unroll
    for (int off = 16; off; off >>= 1)
#pragma unroll
        for (int c = 0; c < NCLS; c++)
            sm[c] += __shfl_xor_sync(0xffffffffu, sm[c], off);
    if (lid == 0)
#pragma unroll
        for (int c = 0; c < NCLS; c++) wreds[wid][c] = sm[c];
    __syncthreads();
    float inv[NCLS];
#pragma unroll
    for (int c = 0; c < NCLS; c++) {
        float s = wreds[0][c];
#pragma unroll
        for (int w = 1; w < 8; w++) s += wreds[w][c];
        inv[c] = 1.0f / s;
    }

    float* o0 = out + (size_t)t0 * BD * NCLS + (size_t)b * NCLS;
#pragma unroll
    for (int c = 0; c < NCLS; c++) o0[c] = va[c] * inv[c];
#pragma unroll
    for (int c = 0; c < NCLS; c++) o0[BD * NCLS + c] = vb[c] * inv[c];
}

// ---------------- launch -----------------------------------------------------
extern "C" void kernel_launch(void* const* d_in, const int* in_sizes, int n_in,
                              void* d_out, int out_size) {
    (void)in_sizes; (void)n_in; (void)out_size;
    const int*   x    = (const int*)  d_in[0];
    const float* emb  = (const float*)d_in[1];
    const float* W_ih = (const float*)d_in[2];
    const float* W_hh = (const float*)d_in[3];
    const float* b_ih = (const float*)d_in[4];
    const float* b_hh = (const float*)d_in[5];
    const float* W1   = (const float*)d_in[6];
    const float* b1   = (const float*)d_in[7];
    const float* W2   = (const float*)d_in[8];
    const float* b2   = (const float*)d_in[9];

    table_kernel<<<VOCAB / 8, 256>>>(emb, W_ih, b_ih, b_hh);
    lstm_kernel<<<BD / 4, 64>>>(x, W_hh);
    head_softmax_kernel<<<BD, 256>>>(W1, b1, W2, b2, (float*)d_out);
}